// round 14
// baseline (speedup 1.0000x reference)
#include <cuda_runtime.h>
#include <cuda_bf16.h>
#include <stdint.h>
#include <math.h>

// Problem constants
#define Bsz  2
#define Lseq 1024
#define Dm   768
#define NHn  12
#define HDd  64
#define NLn  6
#define MLPd 3072
#define NTOK (Bsz * Lseq)   // 2048
#define NBH  (Bsz * NHn)    // 24

// TF32 rounding (round-to-nearest, matches cuBLAS input conversion)
__device__ __forceinline__ float tf32r(float x) {
    asm("cvt.rna.tf32.f32 %0, %0;" : "+f"(x));
    return x;
}
__device__ __forceinline__ float4 tf32r4(float4 v) {
    v.x = tf32r(v.x); v.y = tf32r(v.y); v.z = tf32r(v.z); v.w = tf32r(v.w);
    return v;
}

// m16n8k8 tf32 mma, fp32 accumulate
__device__ __forceinline__ void mma_tf32(float* c, const float* a, const float* b) {
    asm volatile(
        "mma.sync.aligned.m16n8k8.row.col.f32.tf32.tf32.f32 "
        "{%0,%1,%2,%3}, {%4,%5,%6,%7}, {%8,%9}, {%0,%1,%2,%3};\n"
        : "+f"(c[0]), "+f"(c[1]), "+f"(c[2]), "+f"(c[3])
        : "r"(__float_as_uint(a[0])), "r"(__float_as_uint(a[1])),
          "r"(__float_as_uint(a[2])), "r"(__float_as_uint(a[3])),
          "r"(__float_as_uint(b[0])), "r"(__float_as_uint(b[1])));
}

// cp.async helpers
__device__ __forceinline__ void cp16(uint32_t s, const void* g) {
    asm volatile("cp.async.cg.shared.global [%0], [%1], 16;\n" :: "r"(s), "l"(g));
}
#define CP_COMMIT() asm volatile("cp.async.commit_group;\n")
#define CP_WAIT1()  asm volatile("cp.async.wait_group 1;\n")
#define CP_WAIT0()  asm volatile("cp.async.wait_group 0;\n")

// ---------------------------------------------------------------------------
// Scratch (static device globals; no allocation)
// ---------------------------------------------------------------------------
__device__ float g_x     [NTOK * Dm];
__device__ float g_h     [NTOK * Dm];        // LN out (rounded); rounded final x
__device__ float g_qkv   [NTOK * 3 * Dm];
__device__ float g_o     [NTOK * Dm];
__device__ float g_mlp   [NTOK * MLPd];      // also rounded spatial at layer 0
__device__ float g_cond  [Bsz * Dm];
// pre-rounded weight copies
__device__ float g_wspat [Dm * Dm];
__device__ float g_wqkv  [NLn * Dm * 3 * Dm];
__device__ float g_wproj [NLn * Dm * Dm];
__device__ float g_wm1   [NLn * Dm * MLPd];
__device__ float g_wm2   [NLn * MLPd * Dm];
__device__ float g_wout  [Dm * Dm];

// ---------------------------------------------------------------------------
// Elementwise tf32 round-copy (float4), n4 = n/4
// ---------------------------------------------------------------------------
__global__ void round_kernel(const float* __restrict__ src, float* __restrict__ dst,
                             int n4) {
    int i = blockIdx.x * blockDim.x + threadIdx.x;
    if (i < n4) ((float4*)dst)[i] = tf32r4(((const float4*)src)[i]);
}

// ---------------------------------------------------------------------------
// cond_out[b,n] = ce[b,:] @ cond_w[:,n] + cond_b[n]   (exact fp32, tiny)
// ---------------------------------------------------------------------------
__global__ void cond_kernel(const float* __restrict__ ce,
                            const float* __restrict__ w,
                            const float* __restrict__ cb,
                            float* __restrict__ out) {
    int idx = blockIdx.x * blockDim.x + threadIdx.x;
    if (idx >= Bsz * Dm) return;
    int b = idx / Dm, n = idx % Dm;
    float s = 0.f;
    const float* cer = ce + b * 1536;
    #pragma unroll 4
    for (int k = 0; k < 1536; k++) s += cer[k] * w[k * Dm + n];
    out[idx] = s + cb[n];
}

// ---------------------------------------------------------------------------
// TF32 tensor-core GEMM, 3-stage cp.async pipeline (1 sync per k-chunk).
// Inputs PRE-ROUNDED to tf32. C[M,N] = A[M,K] @ B[K,N] (+bias+cond+gelu+res)
// Tiles 128x128x32, 256 threads = 8 warps (4m x 2n), 2 blocks/SM.
// ---------------------------------------------------------------------------
#define TBM 128
#define TBN 128
#define TBK 32
#define ASTR 36
#define BSTR 132
#define ABUF (128 * ASTR)
#define BBUF (32 * BSTR)
#define GEMM_DSMEM (3 * (ABUF + BBUF) * 4)   // 105984 bytes (3 stages)

template<bool BIAS, bool GELU_F, bool RES, bool COND>
__global__ __launch_bounds__(256, 2)
void mma_gemm(const float* __restrict__ A, const float* __restrict__ Bm,
              const float* __restrict__ bias, const float* __restrict__ res,
              const float* __restrict__ cond, float* __restrict__ C,
              int M, int N, int K) {
    extern __shared__ float dsm[];
    float* AsB = dsm;                   // [3][128][ASTR]
    float* BsB = dsm + 3 * ABUF;        // [3][32][BSTR]
    const uint32_t aS = (uint32_t)__cvta_generic_to_shared(AsB);
    const uint32_t bS = (uint32_t)__cvta_generic_to_shared(BsB);

    const int tid  = threadIdx.x;
    const int bm   = blockIdx.y * TBM;
    const int bn   = blockIdx.x * TBN;
    const int warp = tid >> 5, lane = tid & 31;
    const int wm = warp >> 1, wn = warp & 1;
    const int gid = lane >> 2, tig = lane & 3;
    const int m_base = wm * 32, n_base = wn * 64;

    const int ar = tid >> 3;
    const int ac = (tid & 7) * 4;
    const int br = tid >> 3;
    const int bc = (tid & 7) * 16;

    float acc[2][8][4];
    #pragma unroll
    for (int mt = 0; mt < 2; mt++)
        #pragma unroll
        for (int nt = 0; nt < 8; nt++)
            #pragma unroll
            for (int i = 0; i < 4; i++) acc[mt][nt][i] = 0.f;

    const int nk = K / TBK;

    auto issue = [&](int k0, int buf) {
        uint32_t ab = aS + (uint32_t)(buf * ABUF) * 4;
        uint32_t bb = bS + (uint32_t)(buf * BBUF) * 4;
        #pragma unroll
        for (int i = 0; i < 4; i++)
            cp16(ab + (uint32_t)((ar + i * 32) * ASTR + ac) * 4,
                 &A[(size_t)(bm + ar + i * 32) * K + k0 + ac]);
        #pragma unroll
        for (int i = 0; i < 4; i++)
            cp16(bb + (uint32_t)(br * BSTR + bc + i * 4) * 4,
                 &Bm[(size_t)(k0 + br) * N + bn + bc + i * 4]);
        CP_COMMIT();
    };

    issue(0, 0);
    issue(TBK, 1);

    int cur = 0;
    for (int kc = 0; kc < nk; kc++) {
        if (kc + 1 < nk) { CP_WAIT1(); } else { CP_WAIT0(); }
        __syncthreads();
        if (kc + 2 < nk) {
            int pf = (cur == 0) ? 2 : cur - 1;   // (cur+2)%3
            issue((kc + 2) * TBK, pf);
        }

        const float* As = AsB + cur * ABUF;
        const float* Bs = BsB + cur * BBUF;
        #pragma unroll
        for (int ks = 0; ks < 4; ks++) {
            const int kk = ks * 8;
            float af[2][4], bf[8][2];
            #pragma unroll
            for (int mt = 0; mt < 2; mt++) {
                int r0 = m_base + mt * 16 + gid;
                af[mt][0] = As[r0 * ASTR + kk + tig];
                af[mt][1] = As[(r0 + 8) * ASTR + kk + tig];
                af[mt][2] = As[r0 * ASTR + kk + tig + 4];
                af[mt][3] = As[(r0 + 8) * ASTR + kk + tig + 4];
            }
            #pragma unroll
            for (int nt = 0; nt < 8; nt++) {
                int c0 = n_base + nt * 8 + gid;
                bf[nt][0] = Bs[(kk + tig) * BSTR + c0];
                bf[nt][1] = Bs[(kk + tig + 4) * BSTR + c0];
            }
            #pragma unroll
            for (int mt = 0; mt < 2; mt++)
                #pragma unroll
                for (int nt = 0; nt < 8; nt++)
                    mma_tf32(acc[mt][nt], af[mt], bf[nt]);
        }
        cur = (cur == 2) ? 0 : cur + 1;
    }

    #pragma unroll
    for (int mt = 0; mt < 2; mt++) {
        #pragma unroll
        for (int nt = 0; nt < 8; nt++) {
            int col = bn + n_base + nt * 8 + tig * 2;
            #pragma unroll
            for (int half = 0; half < 2; half++) {
                int row = bm + m_base + mt * 16 + gid + half * 8;
                float vx = acc[mt][nt][half * 2 + 0];
                float vy = acc[mt][nt][half * 2 + 1];
                if (BIAS) { vx += bias[col]; vy += bias[col + 1]; }
                if (COND) {
                    const float* cp = cond + (row >> 10) * N + col;
                    vx += cp[0]; vy += cp[1];
                }
                if (GELU_F) {
                    vx = 0.5f * vx * (1.f + erff(vx * 0.70710678118654752f));
                    vy = 0.5f * vy * (1.f + erff(vy * 0.70710678118654752f));
                    vx = tf32r(vx); vy = tf32r(vy);
                }
                if (RES) {
                    float2 rr = *(const float2*)&res[(size_t)row * N + col];
                    vx += rr.x; vy += rr.y;
                }
                float2 out = make_float2(vx, vy);
                *(float2*)&C[(size_t)row * N + col] = out;
            }
        }
    }
}

// ---------------------------------------------------------------------------
// TBN=64 variant (proj, mlp2, out), 3-stage pipeline. Bit-identical math.
// ---------------------------------------------------------------------------
#define BSTR2 68
#define BBUF2 (32 * BSTR2)
#define GEMM64_DSMEM (3 * (ABUF + BBUF2) * 4)   // 81408 bytes

template<bool BIAS, bool RES>
__global__ __launch_bounds__(256, 2)
void mma_gemm64(const float* __restrict__ A, const float* __restrict__ Bm,
                const float* __restrict__ bias, const float* __restrict__ res,
                float* __restrict__ C, int M, int N, int K) {
    extern __shared__ float dsm[];
    float* AsB = dsm;
    float* BsB = dsm + 3 * ABUF;
    const uint32_t aS = (uint32_t)__cvta_generic_to_shared(AsB);
    const uint32_t bS = (uint32_t)__cvta_generic_to_shared(BsB);

    const int tid  = threadIdx.x;
    const int bm   = blockIdx.y * TBM;
    const int bn   = blockIdx.x * 64;
    const int warp = tid >> 5, lane = tid & 31;
    const int wm = warp >> 1, wn = warp & 1;
    const int gid = lane >> 2, tig = lane & 3;
    const int m_base = wm * 32, n_base = wn * 32;

    const int ar = tid >> 3;
    const int ac = (tid & 7) * 4;
    const int br = tid >> 3;
    const int bc = (tid & 7) * 8;

    float acc[2][4][4];
    #pragma unroll
    for (int mt = 0; mt < 2; mt++)
        #pragma unroll
        for (int nt = 0; nt < 4; nt++)
            #pragma unroll
            for (int i = 0; i < 4; i++) acc[mt][nt][i] = 0.f;

    const int nk = K / TBK;

    auto issue = [&](int k0, int buf) {
        uint32_t ab = aS + (uint32_t)(buf * ABUF) * 4;
        uint32_t bb = bS + (uint32_t)(buf * BBUF2) * 4;
        #pragma unroll
        for (int i = 0; i < 4; i++)
            cp16(ab + (uint32_t)((ar + i * 32) * ASTR + ac) * 4,
                 &A[(size_t)(bm + ar + i * 32) * K + k0 + ac]);
        #pragma unroll
        for (int i = 0; i < 2; i++)
            cp16(bb + (uint32_t)(br * BSTR2 + bc + i * 4) * 4,
                 &Bm[(size_t)(k0 + br) * N + bn + bc + i * 4]);
        CP_COMMIT();
    };

    issue(0, 0);
    issue(TBK, 1);

    int cur = 0;
    for (int kc = 0; kc < nk; kc++) {
        if (kc + 1 < nk) { CP_WAIT1(); } else { CP_WAIT0(); }
        __syncthreads();
        if (kc + 2 < nk) {
            int pf = (cur == 0) ? 2 : cur - 1;
            issue((kc + 2) * TBK, pf);
        }

        const float* As = AsB + cur * ABUF;
        const float* Bs = BsB + cur * BBUF2;
        #pragma unroll
        for (int ks = 0; ks < 4; ks++) {
            const int kk = ks * 8;
            float af[2][4], bf[4][2];
            #pragma unroll
            for (int mt = 0; mt < 2; mt++) {
                int r0 = m_base + mt * 16 + gid;
                af[mt][0] = As[r0 * ASTR + kk + tig];
                af[mt][1] = As[(r0 + 8) * ASTR + kk + tig];
                af[mt][2] = As[r0 * ASTR + kk + tig + 4];
                af[mt][3] = As[(r0 + 8) * ASTR + kk + tig + 4];
            }
            #pragma unroll
            for (int nt = 0; nt < 4; nt++) {
                int c0 = n_base + nt * 8 + gid;
                bf[nt][0] = Bs[(kk + tig) * BSTR2 + c0];
                bf[nt][1] = Bs[(kk + tig + 4) * BSTR2 + c0];
            }
            #pragma unroll
            for (int mt = 0; mt < 2; mt++)
                #pragma unroll
                for (int nt = 0; nt < 4; nt++)
                    mma_tf32(acc[mt][nt], af[mt], bf[nt]);
        }
        cur = (cur == 2) ? 0 : cur + 1;
    }

    #pragma unroll
    for (int mt = 0; mt < 2; mt++) {
        #pragma unroll
        for (int nt = 0; nt < 4; nt++) {
            int col = bn + n_base + nt * 8 + tig * 2;
            #pragma unroll
            for (int half = 0; half < 2; half++) {
                int row = bm + m_base + mt * 16 + gid + half * 8;
                float vx = acc[mt][nt][half * 2 + 0];
                float vy = acc[mt][nt][half * 2 + 1];
                if (BIAS) { vx += bias[col]; vy += bias[col + 1]; }
                if (RES) {
                    float2 rr = *(const float2*)&res[(size_t)row * N + col];
                    vx += rr.x; vy += rr.y;
                }
                float2 out = make_float2(vx, vy);
                *(float2*)&C[(size_t)row * N + col] = out;
            }
        }
    }
}

// ---------------------------------------------------------------------------
// LayerNorm: one block per token row; output rounded to tf32 (GEMM-A only).
// ---------------------------------------------------------------------------
__global__ __launch_bounds__(256)
void layernorm_kernel(const float* __restrict__ x, const float* __restrict__ g,
                      const float* __restrict__ b, float* __restrict__ out) {
    int row = blockIdx.x;
    int t = threadIdx.x;
    const float* xr = x + (size_t)row * Dm;
    float v0 = xr[t], v1 = xr[t + 256], v2 = xr[t + 512];
    float s = v0 + v1 + v2;
    float q = v0 * v0 + v1 * v1 + v2 * v2;
    #pragma unroll
    for (int o = 16; o > 0; o >>= 1) {
        s += __shfl_xor_sync(0xffffffffu, s, o);
        q += __shfl_xor_sync(0xffffffffu, q, o);
    }
    __shared__ float ss[8], sq[8];
    int wid = t >> 5, lane = t & 31;
    if (!lane) { ss[wid] = s; sq[wid] = q; }
    __syncthreads();
    if (t == 0) {
        float S = 0.f, Q = 0.f;
        #pragma unroll
        for (int i = 0; i < 8; i++) { S += ss[i]; Q += sq[i]; }
        float m = S * (1.f / Dm);
        float var = Q * (1.f / Dm) - m * m;
        ss[0] = m;
        sq[0] = rsqrtf(var + 1e-5f);
    }
    __syncthreads();
    float m = ss[0], r = sq[0];
    float* orow = out + (size_t)row * Dm;
    orow[t]       = tf32r((v0 - m) * r * g[t]       + b[t]);
    orow[t + 256] = tf32r((v1 - m) * r * g[t + 256] + b[t + 256]);
    orow[t + 512] = tf32r((v2 - m) * r * g[t + 512] + b[t + 512]);
}

// ---------------------------------------------------------------------------
// Fused RMSNorm + RoPE on q,k (rounded outputs) + round v in place.
// fp64 transcendentals (fast-math-proof; proven pass).
// ---------------------------------------------------------------------------
__global__ __launch_bounds__(768)
void rmsrope_kernel(float* __restrict__ qkv,
                    const float* __restrict__ qs,
                    const float* __restrict__ ks) {
    int token = blockIdx.x;
    int w = threadIdx.x >> 5;
    int lane = threadIdx.x & 31;
    int isK = (w >= NHn);
    int h = isK ? w - NHn : w;
    float* base = qkv + (size_t)token * (3 * Dm) + (isK ? Dm : 0) + h * HDd;
    const float* sc = isK ? ks : qs;

    float x0 = base[2 * lane], x1 = base[2 * lane + 1];
    float s = x0 * x0 + x1 * x1;
    #pragma unroll
    for (int o = 16; o > 0; o >>= 1) s += __shfl_xor_sync(0xffffffffu, s, o);
    float r = rsqrtf(s * (1.f / HDd) + 1e-6f);
    float y0 = x0 * r * sc[2 * lane];
    float y1 = x1 * r * sc[2 * lane + 1];

    int l = token & (Lseq - 1);
    int col = l & 31, rowp = l >> 5;
    double pos, fidx;
    if (lane < 16) { pos = (double)col;  fidx = (double)lane; }
    else           { pos = (double)rowp; fidx = (double)(lane - 16); }
    double omega = exp(fidx * -0.5756462732485115);
    double ang = pos * omega;
    float c  = (float)cos(ang);
    float sn = (float)sin(ang);
    base[2 * lane]     = tf32r(c * y0 - sn * y1);
    base[2 * lane + 1] = tf32r(sn * y0 + c * y1);

    float* vb = qkv + (size_t)token * (3 * Dm) + 2 * Dm;
    vb[threadIdx.x] = tf32r(vb[threadIdx.x]);
}

// ---------------------------------------------------------------------------
// Fused flash attention (FA2 warp layout). Grid (L/128, NBH), 256 thr = 8 warps.
// ---------------------------------------------------------------------------
#define FLQ 128
#define FLK 64
#define QSTR 68
#define KSTR 68
#define VSTR 68
#define KOFF (FLQ * QSTR)                 // 8704 floats
#define VOFF (KOFF + 2 * FLK * KSTR)      // 17408 floats
#define FL_DSMEM ((VOFF + 2 * FLK * VSTR) * 4)   // 104448 bytes

__global__ __launch_bounds__(256, 2)
void flash_mma(const float* __restrict__ qkv, const float* __restrict__ dens,
               const float* __restrict__ dscale, const float* __restrict__ dbias,
               int layer, float* __restrict__ o) {
    extern __shared__ float dsm[];
    float* Qs = dsm;
    float* Ks = dsm + KOFF;
    float* Vs = dsm + VOFF;
    const uint32_t qS = (uint32_t)__cvta_generic_to_shared(Qs);
    const uint32_t vS = (uint32_t)__cvta_generic_to_shared(Vs);

    const int tid = threadIdx.x;
    const int ml  = blockIdx.x * FLQ;
    const int z   = blockIdx.y;
    const int b = z / NHn, h = z % NHn;
    const int warp = tid >> 5, lane = tid & 31;
    const int gid = lane >> 2, tig = lane & 3;
    const int wRow = warp * 16;

    const float* Qb = qkv + (size_t)(b * Lseq + ml) * (3 * Dm) + h * HDd;
    const float* Kb = qkv + (size_t)(b * Lseq) * (3 * Dm) + Dm + h * HDd;
    const float* Vb = Kb + Dm;

    {
        int r = tid >> 1, cb = (tid & 1) * 32;
        #pragma unroll
        for (int i = 0; i < 8; i++)
            cp16(qS + (uint32_t)(r * QSTR + cb + i * 4) * 4,
                 Qb + (size_t)r * (3 * Dm) + cb + i * 4);
    }
    const int kkey = tid >> 2;
    const int kdb  = (tid & 3) * 4;
    float4 kr[4];
    #pragma unroll
    for (int i = 0; i < 4; i++)
        kr[i] = *(const float4*)&Kb[(size_t)kkey * (3 * Dm) + kdb + i * 16];
    const int vr = tid >> 2, vcb = (tid & 3) * 16;
    #pragma unroll
    for (int i = 0; i < 4; i++)
        cp16(vS + (uint32_t)(vr * VSTR + vcb + i * 4) * 4,
             Vb + (size_t)vr * (3 * Dm) + vcb + i * 4);
    CP_COMMIT();

    const int r0g = ml + wRow + gid;
    const float dsc = dscale[layer], dbi = dbias[layer];
    const float bv0 = dsc * dens[b * Lseq + r0g] + dbi;
    const float bv1 = dsc * dens[b * Lseq + r0g + 8] + dbi;
    float m0 = -1e30f, m1 = -1e30f, l0 = 0.f, l1 = 0.f;

    float oacc[8][4];
    #pragma unroll
    for (int nt = 0; nt < 8; nt++)
        #pragma unroll
        for (int i = 0; i < 4; i++) oacc[nt][i] = 0.f;

    const int ntile = Lseq / FLK;
    for (int kt = 0; kt < ntile; kt++) {
        const int cur = kt & 1;
        float* Kc = Ks + cur * (FLK * KSTR);
        const float* Vc = Vs + cur * (FLK * VSTR);

        #pragma unroll
        for (int i = 0; i < 4; i++) {
            int d0 = kdb + i * 16;
            Kc[(d0 + 0) * KSTR + kkey] = kr[i].x;
            Kc[(d0 + 1) * KSTR + kkey] = kr[i].y;
            Kc[(d0 + 2) * KSTR + kkey] = kr[i].z;
            Kc[(d0 + 3) * KSTR + kkey] = kr[i].w;
        }
        if (kt + 1 < ntile) {
            const int kg = (kt + 1) * FLK;
            #pragma unroll
            for (int i = 0; i < 4; i++)
                kr[i] = *(const float4*)&Kb[(size_t)(kg + kkey) * (3 * Dm) + kdb + i * 16];
            uint32_t vb2 = vS + (uint32_t)((cur ^ 1) * FLK * VSTR) * 4;
            #pragma unroll
            for (int i = 0; i < 4; i++)
                cp16(vb2 + (uint32_t)(vr * VSTR + vcb + i * 4) * 4,
                     Vb + (size_t)(kg + vr) * (3 * Dm) + vcb + i * 4);
            CP_COMMIT();
            CP_WAIT1();
        } else {
            CP_WAIT0();
        }
        __syncthreads();

        float sacc[8][4];
        #pragma unroll
        for (int nt = 0; nt < 8; nt++)
            #pragma unroll
            for (int i = 0; i < 4; i++) sacc[nt][i] = 0.f;

        #pragma unroll
        for (int kkc = 0; kkc < 8; kkc++) {
            const int kk = kkc * 8;
            float aq[4];
            aq[0] = Qs[(wRow + gid) * QSTR + kk + tig];
            aq[1] = Qs[(wRow + gid + 8) * QSTR + kk + tig];
            aq[2] = Qs[(wRow + gid) * QSTR + kk + tig + 4];
            aq[3] = Qs[(wRow + gid + 8) * QSTR + kk + tig + 4];
            #pragma unroll
            for (int nt = 0; nt < 8; nt++) {
                float bf[2];
                bf[0] = Kc[(kk + tig) * KSTR + nt * 8 + gid];
                bf[1] = Kc[(kk + tig + 4) * KSTR + nt * 8 + gid];
                mma_tf32(sacc[nt], aq, bf);
            }
        }

        float tm0 = -1e30f, tm1 = -1e30f;
        #pragma unroll
        for (int nt = 0; nt < 8; nt++) {
            sacc[nt][0] = sacc[nt][0] * 0.125f + bv0;
            sacc[nt][1] = sacc[nt][1] * 0.125f + bv0;
            sacc[nt][2] = sacc[nt][2] * 0.125f + bv1;
            sacc[nt][3] = sacc[nt][3] * 0.125f + bv1;
            tm0 = fmaxf(tm0, fmaxf(sacc[nt][0], sacc[nt][1]));
            tm1 = fmaxf(tm1, fmaxf(sacc[nt][2], sacc[nt][3]));
        }
        tm0 = fmaxf(tm0, __shfl_xor_sync(0xffffffffu, tm0, 1));
        tm0 = fmaxf(tm0, __shfl_xor_sync(0xffffffffu, tm0, 2));
        tm1 = fmaxf(tm1, __shfl_xor_sync(0xffffffffu, tm1, 1));
        tm1 = fmaxf(tm1, __shfl_xor_sync(0xffffffffu, tm1, 2));

        const float mn0 = fmaxf(m0, tm0), mn1 = fmaxf(m1, tm1);
        const float sc0 = __expf(m0 - mn0), sc1 = __expf(m1 - mn1);
        float ps0 = 0.f, ps1 = 0.f;
        #pragma unroll
        for (int nt = 0; nt < 8; nt++) {
            float p0 = __expf(sacc[nt][0] - mn0);
            float p1 = __expf(sacc[nt][1] - mn0);
            float p2 = __expf(sacc[nt][2] - mn1);
            float p3 = __expf(sacc[nt][3] - mn1);
            ps0 += p0 + p1; ps1 += p2 + p3;
            sacc[nt][0] = tf32r(p0); sacc[nt][1] = tf32r(p1);
            sacc[nt][2] = tf32r(p2); sacc[nt][3] = tf32r(p3);
            oacc[nt][0] *= sc0; oacc[nt][1] *= sc0;
            oacc[nt][2] *= sc1; oacc[nt][3] *= sc1;
        }
        ps0 += __shfl_xor_sync(0xffffffffu, ps0, 1);
        ps0 += __shfl_xor_sync(0xffffffffu, ps0, 2);
        ps1 += __shfl_xor_sync(0xffffffffu, ps1, 1);
        ps1 += __shfl_xor_sync(0xffffffffu, ps1, 2);
        l0 = l0 * sc0 + ps0; l1 = l1 * sc1 + ps1;
        m0 = mn0; m1 = mn1;

        const int s1l = (lane & ~3) + (tig >> 1);
        const int s2l = s1l + 2;
        const bool odd = (tig & 1);
        #pragma unroll
        for (int snt = 0; snt < 8; snt++) {
            float v00 = __shfl_sync(0xffffffffu, sacc[snt][0], s1l);
            float v01 = __shfl_sync(0xffffffffu, sacc[snt][1], s1l);
            float v20 = __shfl_sync(0xffffffffu, sacc[snt][2], s1l);
            float v21 = __shfl_sync(0xffffffffu, sacc[snt][3], s1l);
            float w00 = __shfl_sync(0xffffffffu, sacc[snt][0], s2l);
            float w01 = __shfl_sync(0xffffffffu, sacc[snt][1], s2l);
            float w20 = __shfl_sync(0xffffffffu, sacc[snt][2], s2l);
            float w21 = __shfl_sync(0xffffffffu, sacc[snt][3], s2l);
            float af[4];
            af[0] = odd ? v01 : v00;
            af[1] = odd ? v21 : v20;
            af[2] = odd ? w01 : w00;
            af[3] = odd ? w21 : w20;
            #pragma unroll
            for (int nt = 0; nt < 8; nt++) {
                float bf[2];
                bf[0] = Vc[(snt * 8 + tig) * VSTR + nt * 8 + gid];
                bf[1] = Vc[(snt * 8 + tig + 4) * VSTR + nt * 8 + gid];
                mma_tf32(oacc[nt], af, bf);
            }
        }
        __syncthreads();
    }

    const float inv0 = 1.f / l0, inv1 = 1.f / l1;
    float* ob = o + (size_t)(b * Lseq) * Dm + h * HDd;
    #pragma unroll
    for (int nt = 0; nt < 8; nt++) {
        int col = nt * 8 + tig * 2;
        float2 o0 = make_float2(tf32r(oacc[nt][0] * inv0), tf32r(oacc[nt][1] * inv0));
        float2 o1 = make_float2(tf32r(oacc[nt][2] * inv1), tf32r(oacc[nt][3] * inv1));
        *(float2*)&ob[(size_t)r0g * Dm + col] = o0;
        *(float2*)&ob[(size_t)(r0g + 8) * Dm + col] = o1;
    }
}

// ---------------------------------------------------------------------------
// Launch sequence (graph-capturable: kernel launches only)
// ---------------------------------------------------------------------------
extern "C" void kernel_launch(void* const* d_in, const int* in_sizes, int n_in,
                              void* d_out, int out_size) {
    const float* spatial   = (const float*)d_in[0];
    const float* density   = (const float*)d_in[1];
    const float* ce        = (const float*)d_in[2];
    const float* spatial_w = (const float*)d_in[3];
    const float* spatial_b = (const float*)d_in[4];
    const float* cond_w    = (const float*)d_in[5];
    const float* cond_b    = (const float*)d_in[6];
    const float* ln1_g     = (const float*)d_in[7];
    const float* ln1_b     = (const float*)d_in[8];
    const float* qkv_w     = (const float*)d_in[9];
    const float* q_scale   = (const float*)d_in[10];
    const float* k_scale   = (const float*)d_in[11];
    const float* proj_w    = (const float*)d_in[12];
    const float* proj_b    = (const float*)d_in[13];
    const float* dscale    = (const float*)d_in[14];
    const float* dbias     = (const float*)d_in[15];
    const float* ln2_g     = (const float*)d_in[16];
    const float* ln2_b     = (const float*)d_in[17];
    const float* mlp_w1    = (const float*)d_in[18];
    const float* mlp_b1    = (const float*)d_in[19];
    const float* mlp_w2    = (const float*)d_in[20];
    const float* mlp_b2    = (const float*)d_in[21];
    const float* out_w     = (const float*)d_in[22];
    const float* out_b     = (const float*)d_in[23];

    float *x, *h, *qkv, *o, *mlp, *cond;
    float *wspat, *wqkv, *wproj, *wm1, *wm2, *wout;
    cudaGetSymbolAddress((void**)&x,      g_x);
    cudaGetSymbolAddress((void**)&h,      g_h);
    cudaGetSymbolAddress((void**)&qkv,    g_qkv);
    cudaGetSymbolAddress((void**)&o,      g_o);
    cudaGetSymbolAddress((void**)&mlp,    g_mlp);
    cudaGetSymbolAddress((void**)&cond,   g_cond);
    cudaGetSymbolAddress((void**)&wspat,  g_wspat);
    cudaGetSymbolAddress((void**)&wqkv,   g_wqkv);
    cudaGetSymbolAddress((void**)&wproj,  g_wproj);
    cudaGetSymbolAddress((void**)&wm1,    g_wm1);
    cudaGetSymbolAddress((void**)&wm2,    g_wm2);
    cudaGetSymbolAddress((void**)&wout,   g_wout);

    cudaFuncSetAttribute(mma_gemm<true,  false, false, true >, cudaFuncAttributeMaxDynamicSharedMemorySize, GEMM_DSMEM);
    cudaFuncSetAttribute(mma_gemm<false, false, false, false>, cudaFuncAttributeMaxDynamicSharedMemorySize, GEMM_DSMEM);
    cudaFuncSetAttribute(mma_gemm<true,  true,  false, false>, cudaFuncAttributeMaxDynamicSharedMemorySize, GEMM_DSMEM);
    cudaFuncSetAttribute(mma_gemm64<true, true >, cudaFuncAttributeMaxDynamicSharedMemorySize, GEMM64_DSMEM);
    cudaFuncSetAttribute(mma_gemm64<true, false>, cudaFuncAttributeMaxDynamicSharedMemorySize, GEMM64_DSMEM);
    cudaFuncSetAttribute(flash_mma, cudaFuncAttributeMaxDynamicSharedMemorySize, FL_DSMEM);

    // pre-round weights + spatial input (elementwise, position-independent)
    round_kernel<<<(Dm * Dm / 4 + 255) / 256, 256>>>(spatial_w, wspat, Dm * Dm / 4);
    round_kernel<<<(NLn * Dm * 3 * Dm / 4 + 255) / 256, 256>>>(qkv_w, wqkv, NLn * Dm * 3 * Dm / 4);
    round_kernel<<<(NLn * Dm * Dm / 4 + 255) / 256, 256>>>(proj_w, wproj, NLn * Dm * Dm / 4);
    round_kernel<<<(NLn * Dm * MLPd / 4 + 255) / 256, 256>>>(mlp_w1, wm1, NLn * Dm * MLPd / 4);
    round_kernel<<<(NLn * MLPd * Dm / 4 + 255) / 256, 256>>>(mlp_w2, wm2, NLn * MLPd * Dm / 4);
    round_kernel<<<(Dm * Dm / 4 + 255) / 256, 256>>>(out_w, wout, Dm * Dm / 4);
    round_kernel<<<(NTOK * Dm / 4 + 255) / 256, 256>>>(spatial, mlp, NTOK * Dm / 4);

    cond_kernel<<<(Bsz * Dm + 255) / 256, 256>>>(ce, cond_w, cond_b, cond);
    mma_gemm<true, false, false, true>
        <<<dim3(Dm / TBN, NTOK / TBM), 256, GEMM_DSMEM>>>(
        mlp, wspat, spatial_b, nullptr, cond, x, NTOK, Dm, Dm);

    for (int i = 0; i < NLn; i++) {
        layernorm_kernel<<<NTOK, 256>>>(x, ln1_g + i * Dm, ln1_b + i * Dm, h);

        mma_gemm<false, false, false, false>
            <<<dim3(3 * Dm / TBN, NTOK / TBM), 256, GEMM_DSMEM>>>(
            h, wqkv + (size_t)i * Dm * 3 * Dm, nullptr, nullptr, nullptr,
            qkv, NTOK, 3 * Dm, Dm);

        rmsrope_kernel<<<NTOK, 768>>>(qkv, q_scale + i * HDd, k_scale + i * HDd);

        flash_mma<<<dim3(Lseq / FLQ, NBH), 256, FL_DSMEM>>>(
            qkv, density, dscale, dbias, i, o);

        mma_gemm64<true, true>
            <<<dim3(Dm / 64, NTOK / TBM), 256, GEMM64_DSMEM>>>(
            o, wproj + (size_t)i * Dm * Dm, proj_b + i * Dm, x, x,
            NTOK, Dm, Dm);

        layernorm_kernel<<<NTOK, 256>>>(x, ln2_g + i * Dm, ln2_b + i * Dm, h);

        mma_gemm<true, true, false, false>
            <<<dim3(MLPd / TBN, NTOK / TBM), 256, GEMM_DSMEM>>>(
            h, wm1 + (size_t)i * Dm * MLPd, mlp_b1 + i * MLPd, nullptr,
            nullptr, mlp, NTOK, MLPd, Dm);

        mma_gemm64<true, true>
            <<<dim3(Dm / 64, NTOK / TBM), 256, GEMM64_DSMEM>>>(
            mlp, wm2 + (size_t)i * MLPd * Dm, mlp_b2 + i * Dm, x, x,
            NTOK, Dm, MLPd);
    }

    // rounded copy of x for the final GEMM (x itself stays exact)
    round_kernel<<<(NTOK * Dm / 4 + 255) / 256, 256>>>(x, h, NTOK * Dm / 4);
    mma_gemm64<true, false>
        <<<dim3(Dm / 64, NTOK / TBM), 256, GEMM64_DSMEM>>>(
        h, wout, out_b, nullptr, (float*)d_out, NTOK, Dm, Dm);
}

// round 15
// speedup vs baseline: 2.0333x; 2.0333x over previous
#include <cuda_runtime.h>
#include <cuda_bf16.h>
#include <stdint.h>
#include <math.h>

// Problem constants
#define Bsz  2
#define Lseq 1024
#define Dm   768
#define NHn  12
#define HDd  64
#define NLn  6
#define MLPd 3072
#define NTOK (Bsz * Lseq)   // 2048
#define NBH  (Bsz * NHn)    // 24

// TF32 rounding (round-to-nearest, matches cuBLAS input conversion)
__device__ __forceinline__ float tf32r(float x) {
    asm("cvt.rna.tf32.f32 %0, %0;" : "+f"(x));
    return x;
}
__device__ __forceinline__ float4 tf32r4(float4 v) {
    v.x = tf32r(v.x); v.y = tf32r(v.y); v.z = tf32r(v.z); v.w = tf32r(v.w);
    return v;
}

// m16n8k8 tf32 mma, fp32 accumulate
__device__ __forceinline__ void mma_tf32(float* c, const float* a, const float* b) {
    asm volatile(
        "mma.sync.aligned.m16n8k8.row.col.f32.tf32.tf32.f32 "
        "{%0,%1,%2,%3}, {%4,%5,%6,%7}, {%8,%9}, {%0,%1,%2,%3};\n"
        : "+f"(c[0]), "+f"(c[1]), "+f"(c[2]), "+f"(c[3])
        : "r"(__float_as_uint(a[0])), "r"(__float_as_uint(a[1])),
          "r"(__float_as_uint(a[2])), "r"(__float_as_uint(a[3])),
          "r"(__float_as_uint(b[0])), "r"(__float_as_uint(b[1])));
}

// cp.async helpers
__device__ __forceinline__ void cp16(uint32_t s, const void* g) {
    asm volatile("cp.async.cg.shared.global [%0], [%1], 16;\n" :: "r"(s), "l"(g));
}
#define CP_COMMIT() asm volatile("cp.async.commit_group;\n")
#define CP_WAIT1()  asm volatile("cp.async.wait_group 1;\n")
#define CP_WAIT0()  asm volatile("cp.async.wait_group 0;\n")

// ---------------------------------------------------------------------------
// Scratch (static device globals; no allocation)
// ---------------------------------------------------------------------------
__device__ float g_x     [NTOK * Dm];
__device__ float g_h     [NTOK * Dm];        // LN out (rounded); rounded final x
__device__ float g_qkv   [NTOK * 3 * Dm];
__device__ float g_o     [NTOK * Dm];
__device__ float g_mlp   [NTOK * MLPd];      // also rounded spatial at layer 0
__device__ float g_cond  [Bsz * Dm];
__device__ float2 g_rope [Lseq * 32];        // per (l, lane) cos/sin, layer-invariant
// pre-rounded weight copies
__device__ float g_wspat [Dm * Dm];
__device__ float g_wqkv  [NLn * Dm * 3 * Dm];
__device__ float g_wproj [NLn * Dm * Dm];
__device__ float g_wm1   [NLn * Dm * MLPd];
__device__ float g_wm2   [NLn * MLPd * Dm];
__device__ float g_wout  [Dm * Dm];

// ---------------------------------------------------------------------------
// Elementwise tf32 round-copy (float4), n4 = n/4
// ---------------------------------------------------------------------------
__global__ void round_kernel(const float* __restrict__ src, float* __restrict__ dst,
                             int n4) {
    int i = blockIdx.x * blockDim.x + threadIdx.x;
    if (i < n4) ((float4*)dst)[i] = tf32r4(((const float4*)src)[i]);
}

// ---------------------------------------------------------------------------
// RoPE cos/sin table: identical fp64 math as the previous in-loop version,
// computed ONCE per launch (layer-invariant). Bit-identical values.
// idx = l*32 + lane; pairs 0-15 <- x=l%32, 16-31 <- y=l/32; omega=10000^(-j/16)
// ---------------------------------------------------------------------------
__global__ void rope_table_kernel(float2* __restrict__ tab) {
    int idx = blockIdx.x * blockDim.x + threadIdx.x;
    if (idx >= Lseq * 32) return;
    int l = idx >> 5, lane = idx & 31;
    int col = l & 31, rowp = l >> 5;
    double pos, fidx;
    if (lane < 16) { pos = (double)col;  fidx = (double)lane; }
    else           { pos = (double)rowp; fidx = (double)(lane - 16); }
    double omega = exp(fidx * -0.5756462732485115);
    double ang = pos * omega;
    tab[idx] = make_float2((float)cos(ang), (float)sin(ang));
}

// ---------------------------------------------------------------------------
// cond_out[b,n] = ce[b,:] @ cond_w[:,n] + cond_b[n]   (exact fp32, tiny)
// ---------------------------------------------------------------------------
__global__ void cond_kernel(const float* __restrict__ ce,
                            const float* __restrict__ w,
                            const float* __restrict__ cb,
                            float* __restrict__ out) {
    int idx = blockIdx.x * blockDim.x + threadIdx.x;
    if (idx >= Bsz * Dm) return;
    int b = idx / Dm, n = idx % Dm;
    float s = 0.f;
    const float* cer = ce + b * 1536;
    #pragma unroll 4
    for (int k = 0; k < 1536; k++) s += cer[k] * w[k * Dm + n];
    out[idx] = s + cb[n];
}

// ---------------------------------------------------------------------------
// TF32 tensor-core GEMM, cp.async double-buffered (PROVEN round-12 form).
// Inputs PRE-ROUNDED to tf32. C[M,N] = A[M,K] @ B[K,N] (+bias+cond+gelu+res)
// Tiles 128x128x32, 256 threads = 8 warps (4m x 2n), 2 blocks/SM.
// ---------------------------------------------------------------------------
#define TBM 128
#define TBN 128
#define TBK 32
#define ASTR 36
#define BSTR 132
#define ABUF (128 * ASTR)
#define BBUF (32 * BSTR)
#define GEMM_DSMEM (2 * (ABUF + BBUF) * 4)   // 70656 bytes

template<bool BIAS, bool GELU_F, bool RES, bool COND>
__global__ __launch_bounds__(256, 2)
void mma_gemm(const float* __restrict__ A, const float* __restrict__ Bm,
              const float* __restrict__ bias, const float* __restrict__ res,
              const float* __restrict__ cond, float* __restrict__ C,
              int M, int N, int K) {
    extern __shared__ float dsm[];
    float* AsB = dsm;
    float* BsB = dsm + 2 * ABUF;
    const uint32_t aS = (uint32_t)__cvta_generic_to_shared(AsB);
    const uint32_t bS = (uint32_t)__cvta_generic_to_shared(BsB);

    const int tid  = threadIdx.x;
    const int bm   = blockIdx.y * TBM;
    const int bn   = blockIdx.x * TBN;
    const int warp = tid >> 5, lane = tid & 31;
    const int wm = warp >> 1, wn = warp & 1;
    const int gid = lane >> 2, tig = lane & 3;
    const int m_base = wm * 32, n_base = wn * 64;

    const int ar = tid >> 3;
    const int ac = (tid & 7) * 4;
    const int br = tid >> 3;
    const int bc = (tid & 7) * 16;

    float acc[2][8][4];
    #pragma unroll
    for (int mt = 0; mt < 2; mt++)
        #pragma unroll
        for (int nt = 0; nt < 8; nt++)
            #pragma unroll
            for (int i = 0; i < 4; i++) acc[mt][nt][i] = 0.f;

    const int nk = K / TBK;

    {
        #pragma unroll
        for (int i = 0; i < 4; i++)
            cp16(aS + (uint32_t)((ar + i * 32) * ASTR + ac) * 4,
                 &A[(size_t)(bm + ar + i * 32) * K + ac]);
        #pragma unroll
        for (int i = 0; i < 4; i++)
            cp16(bS + (uint32_t)(br * BSTR + bc + i * 4) * 4,
                 &Bm[(size_t)br * N + bn + bc + i * 4]);
        CP_COMMIT();
    }

    for (int kc = 0; kc < nk; kc++) {
        const int cur = kc & 1;
        if (kc + 1 < nk) {
            const int k0 = (kc + 1) * TBK;
            uint32_t ab = aS + (uint32_t)((cur ^ 1) * ABUF) * 4;
            uint32_t bb = bS + (uint32_t)((cur ^ 1) * BBUF) * 4;
            #pragma unroll
            for (int i = 0; i < 4; i++)
                cp16(ab + (uint32_t)((ar + i * 32) * ASTR + ac) * 4,
                     &A[(size_t)(bm + ar + i * 32) * K + k0 + ac]);
            #pragma unroll
            for (int i = 0; i < 4; i++)
                cp16(bb + (uint32_t)(br * BSTR + bc + i * 4) * 4,
                     &Bm[(size_t)(k0 + br) * N + bn + bc + i * 4]);
            CP_COMMIT();
            CP_WAIT1();
        } else {
            CP_WAIT0();
        }
        __syncthreads();

        const float* As = AsB + cur * ABUF;
        const float* Bs = BsB + cur * BBUF;
        #pragma unroll
        for (int ks = 0; ks < 4; ks++) {
            const int kk = ks * 8;
            float af[2][4], bf[8][2];
            #pragma unroll
            for (int mt = 0; mt < 2; mt++) {
                int r0 = m_base + mt * 16 + gid;
                af[mt][0] = As[r0 * ASTR + kk + tig];
                af[mt][1] = As[(r0 + 8) * ASTR + kk + tig];
                af[mt][2] = As[r0 * ASTR + kk + tig + 4];
                af[mt][3] = As[(r0 + 8) * ASTR + kk + tig + 4];
            }
            #pragma unroll
            for (int nt = 0; nt < 8; nt++) {
                int c0 = n_base + nt * 8 + gid;
                bf[nt][0] = Bs[(kk + tig) * BSTR + c0];
                bf[nt][1] = Bs[(kk + tig + 4) * BSTR + c0];
            }
            #pragma unroll
            for (int mt = 0; mt < 2; mt++)
                #pragma unroll
                for (int nt = 0; nt < 8; nt++)
                    mma_tf32(acc[mt][nt], af[mt], bf[nt]);
        }
        __syncthreads();
    }

    #pragma unroll
    for (int mt = 0; mt < 2; mt++) {
        #pragma unroll
        for (int nt = 0; nt < 8; nt++) {
            int col = bn + n_base + nt * 8 + tig * 2;
            #pragma unroll
            for (int half = 0; half < 2; half++) {
                int row = bm + m_base + mt * 16 + gid + half * 8;
                float vx = acc[mt][nt][half * 2 + 0];
                float vy = acc[mt][nt][half * 2 + 1];
                if (BIAS) { vx += bias[col]; vy += bias[col + 1]; }
                if (COND) {
                    const float* cp = cond + (row >> 10) * N + col;
                    vx += cp[0]; vy += cp[1];
                }
                if (GELU_F) {
                    vx = 0.5f * vx * (1.f + erff(vx * 0.70710678118654752f));
                    vy = 0.5f * vy * (1.f + erff(vy * 0.70710678118654752f));
                    vx = tf32r(vx); vy = tf32r(vy);
                }
                if (RES) {
                    float2 rr = *(const float2*)&res[(size_t)row * N + col];
                    vx += rr.x; vy += rr.y;
                }
                float2 out = make_float2(vx, vy);
                *(float2*)&C[(size_t)row * N + col] = out;
            }
        }
    }
}

// ---------------------------------------------------------------------------
// LayerNorm: one block per token row; output rounded to tf32 (GEMM-A only).
// ---------------------------------------------------------------------------
__global__ __launch_bounds__(256)
void layernorm_kernel(const float* __restrict__ x, const float* __restrict__ g,
                      const float* __restrict__ b, float* __restrict__ out) {
    int row = blockIdx.x;
    int t = threadIdx.x;
    const float* xr = x + (size_t)row * Dm;
    float v0 = xr[t], v1 = xr[t + 256], v2 = xr[t + 512];
    float s = v0 + v1 + v2;
    float q = v0 * v0 + v1 * v1 + v2 * v2;
    #pragma unroll
    for (int o = 16; o > 0; o >>= 1) {
        s += __shfl_xor_sync(0xffffffffu, s, o);
        q += __shfl_xor_sync(0xffffffffu, q, o);
    }
    __shared__ float ss[8], sq[8];
    int wid = t >> 5, lane = t & 31;
    if (!lane) { ss[wid] = s; sq[wid] = q; }
    __syncthreads();
    if (t == 0) {
        float S = 0.f, Q = 0.f;
        #pragma unroll
        for (int i = 0; i < 8; i++) { S += ss[i]; Q += sq[i]; }
        float m = S * (1.f / Dm);
        float var = Q * (1.f / Dm) - m * m;
        ss[0] = m;
        sq[0] = rsqrtf(var + 1e-5f);
    }
    __syncthreads();
    float m = ss[0], r = sq[0];
    float* orow = out + (size_t)row * Dm;
    orow[t]       = tf32r((v0 - m) * r * g[t]       + b[t]);
    orow[t + 256] = tf32r((v1 - m) * r * g[t + 256] + b[t + 256]);
    orow[t + 512] = tf32r((v2 - m) * r * g[t + 512] + b[t + 512]);
}

// ---------------------------------------------------------------------------
// Fused RMSNorm + RoPE on q,k (rounded outputs) + round v in place.
// cos/sin from precomputed table (bit-identical to in-line fp64 version).
// ---------------------------------------------------------------------------
__global__ __launch_bounds__(768)
void rmsrope_kernel(float* __restrict__ qkv,
                    const float* __restrict__ qs,
                    const float* __restrict__ ks,
                    const float2* __restrict__ rope) {
    int token = blockIdx.x;
    int w = threadIdx.x >> 5;
    int lane = threadIdx.x & 31;
    int isK = (w >= NHn);
    int h = isK ? w - NHn : w;
    float* base = qkv + (size_t)token * (3 * Dm) + (isK ? Dm : 0) + h * HDd;
    const float* sc = isK ? ks : qs;

    float x0 = base[2 * lane], x1 = base[2 * lane + 1];
    float s = x0 * x0 + x1 * x1;
    #pragma unroll
    for (int o = 16; o > 0; o >>= 1) s += __shfl_xor_sync(0xffffffffu, s, o);
    float r = rsqrtf(s * (1.f / HDd) + 1e-6f);
    float y0 = x0 * r * sc[2 * lane];
    float y1 = x1 * r * sc[2 * lane + 1];

    int l = token & (Lseq - 1);
    float2 cs = rope[l * 32 + lane];
    float c = cs.x, sn = cs.y;
    base[2 * lane]     = tf32r(c * y0 - sn * y1);
    base[2 * lane + 1] = tf32r(sn * y0 + c * y1);

    float* vb = qkv + (size_t)token * (3 * Dm) + 2 * Dm;
    vb[threadIdx.x] = tf32r(vb[threadIdx.x]);
}

// ---------------------------------------------------------------------------
// Fused flash attention (FA2 warp layout). Grid (L/128, NBH), 256 thr = 8 warps.
// ---------------------------------------------------------------------------
#define FLQ 128
#define FLK 64
#define QSTR 68
#define KSTR 68
#define VSTR 68
#define KOFF (FLQ * QSTR)                 // 8704 floats
#define VOFF (KOFF + 2 * FLK * KSTR)      // 17408 floats
#define FL_DSMEM ((VOFF + 2 * FLK * VSTR) * 4)   // 104448 bytes

__global__ __launch_bounds__(256, 2)
void flash_mma(const float* __restrict__ qkv, const float* __restrict__ dens,
               const float* __restrict__ dscale, const float* __restrict__ dbias,
               int layer, float* __restrict__ o) {
    extern __shared__ float dsm[];
    float* Qs = dsm;
    float* Ks = dsm + KOFF;
    float* Vs = dsm + VOFF;
    const uint32_t qS = (uint32_t)__cvta_generic_to_shared(Qs);
    const uint32_t vS = (uint32_t)__cvta_generic_to_shared(Vs);

    const int tid = threadIdx.x;
    const int ml  = blockIdx.x * FLQ;
    const int z   = blockIdx.y;
    const int b = z / NHn, h = z % NHn;
    const int warp = tid >> 5, lane = tid & 31;
    const int gid = lane >> 2, tig = lane & 3;
    const int wRow = warp * 16;

    const float* Qb = qkv + (size_t)(b * Lseq + ml) * (3 * Dm) + h * HDd;
    const float* Kb = qkv + (size_t)(b * Lseq) * (3 * Dm) + Dm + h * HDd;
    const float* Vb = Kb + Dm;

    {
        int r = tid >> 1, cb = (tid & 1) * 32;
        #pragma unroll
        for (int i = 0; i < 8; i++)
            cp16(qS + (uint32_t)(r * QSTR + cb + i * 4) * 4,
                 Qb + (size_t)r * (3 * Dm) + cb + i * 4);
    }
    const int kkey = tid >> 2;
    const int kdb  = (tid & 3) * 4;
    float4 kr[4];
    #pragma unroll
    for (int i = 0; i < 4; i++)
        kr[i] = *(const float4*)&Kb[(size_t)kkey * (3 * Dm) + kdb + i * 16];
    const int vr = tid >> 2, vcb = (tid & 3) * 16;
    #pragma unroll
    for (int i = 0; i < 4; i++)
        cp16(vS + (uint32_t)(vr * VSTR + vcb + i * 4) * 4,
             Vb + (size_t)vr * (3 * Dm) + vcb + i * 4);
    CP_COMMIT();

    const int r0g = ml + wRow + gid;
    const float dsc = dscale[layer], dbi = dbias[layer];
    const float bv0 = dsc * dens[b * Lseq + r0g] + dbi;
    const float bv1 = dsc * dens[b * Lseq + r0g + 8] + dbi;
    float m0 = -1e30f, m1 = -1e30f, l0 = 0.f, l1 = 0.f;

    float oacc[8][4];
    #pragma unroll
    for (int nt = 0; nt < 8; nt++)
        #pragma unroll
        for (int i = 0; i < 4; i++) oacc[nt][i] = 0.f;

    const int ntile = Lseq / FLK;
    for (int kt = 0; kt < ntile; kt++) {
        const int cur = kt & 1;
        float* Kc = Ks + cur * (FLK * KSTR);
        const float* Vc = Vs + cur * (FLK * VSTR);

        #pragma unroll
        for (int i = 0; i < 4; i++) {
            int d0 = kdb + i * 16;
            Kc[(d0 + 0) * KSTR + kkey] = kr[i].x;
            Kc[(d0 + 1) * KSTR + kkey] = kr[i].y;
            Kc[(d0 + 2) * KSTR + kkey] = kr[i].z;
            Kc[(d0 + 3) * KSTR + kkey] = kr[i].w;
        }
        if (kt + 1 < ntile) {
            const int kg = (kt + 1) * FLK;
            #pragma unroll
            for (int i = 0; i < 4; i++)
                kr[i] = *(const float4*)&Kb[(size_t)(kg + kkey) * (3 * Dm) + kdb + i * 16];
            uint32_t vb2 = vS + (uint32_t)((cur ^ 1) * FLK * VSTR) * 4;
            #pragma unroll
            for (int i = 0; i < 4; i++)
                cp16(vb2 + (uint32_t)(vr * VSTR + vcb + i * 4) * 4,
                     Vb + (size_t)(kg + vr) * (3 * Dm) + vcb + i * 4);
            CP_COMMIT();
            CP_WAIT1();
        } else {
            CP_WAIT0();
        }
        __syncthreads();

        float sacc[8][4];
        #pragma unroll
        for (int nt = 0; nt < 8; nt++)
            #pragma unroll
            for (int i = 0; i < 4; i++) sacc[nt][i] = 0.f;

        #pragma unroll
        for (int kkc = 0; kkc < 8; kkc++) {
            const int kk = kkc * 8;
            float aq[4];
            aq[0] = Qs[(wRow + gid) * QSTR + kk + tig];
            aq[1] = Qs[(wRow + gid + 8) * QSTR + kk + tig];
            aq[2] = Qs[(wRow + gid) * QSTR + kk + tig + 4];
            aq[3] = Qs[(wRow + gid + 8) * QSTR + kk + tig + 4];
            #pragma unroll
            for (int nt = 0; nt < 8; nt++) {
                float bf[2];
                bf[0] = Kc[(kk + tig) * KSTR + nt * 8 + gid];
                bf[1] = Kc[(kk + tig + 4) * KSTR + nt * 8 + gid];
                mma_tf32(sacc[nt], aq, bf);
            }
        }

        float tm0 = -1e30f, tm1 = -1e30f;
        #pragma unroll
        for (int nt = 0; nt < 8; nt++) {
            sacc[nt][0] = sacc[nt][0] * 0.125f + bv0;
            sacc[nt][1] = sacc[nt][1] * 0.125f + bv0;
            sacc[nt][2] = sacc[nt][2] * 0.125f + bv1;
            sacc[nt][3] = sacc[nt][3] * 0.125f + bv1;
            tm0 = fmaxf(tm0, fmaxf(sacc[nt][0], sacc[nt][1]));
            tm1 = fmaxf(tm1, fmaxf(sacc[nt][2], sacc[nt][3]));
        }
        tm0 = fmaxf(tm0, __shfl_xor_sync(0xffffffffu, tm0, 1));
        tm0 = fmaxf(tm0, __shfl_xor_sync(0xffffffffu, tm0, 2));
        tm1 = fmaxf(tm1, __shfl_xor_sync(0xffffffffu, tm1, 1));
        tm1 = fmaxf(tm1, __shfl_xor_sync(0xffffffffu, tm1, 2));

        const float mn0 = fmaxf(m0, tm0), mn1 = fmaxf(m1, tm1);
        const float sc0 = __expf(m0 - mn0), sc1 = __expf(m1 - mn1);
        float ps0 = 0.f, ps1 = 0.f;
        #pragma unroll
        for (int nt = 0; nt < 8; nt++) {
            float p0 = __expf(sacc[nt][0] - mn0);
            float p1 = __expf(sacc[nt][1] - mn0);
            float p2 = __expf(sacc[nt][2] - mn1);
            float p3 = __expf(sacc[nt][3] - mn1);
            ps0 += p0 + p1; ps1 += p2 + p3;
            sacc[nt][0] = tf32r(p0); sacc[nt][1] = tf32r(p1);
            sacc[nt][2] = tf32r(p2); sacc[nt][3] = tf32r(p3);
            oacc[nt][0] *= sc0; oacc[nt][1] *= sc0;
            oacc[nt][2] *= sc1; oacc[nt][3] *= sc1;
        }
        ps0 += __shfl_xor_sync(0xffffffffu, ps0, 1);
        ps0 += __shfl_xor_sync(0xffffffffu, ps0, 2);
        ps1 += __shfl_xor_sync(0xffffffffu, ps1, 1);
        ps1 += __shfl_xor_sync(0xffffffffu, ps1, 2);
        l0 = l0 * sc0 + ps0; l1 = l1 * sc1 + ps1;
        m0 = mn0; m1 = mn1;

        const int s1l = (lane & ~3) + (tig >> 1);
        const int s2l = s1l + 2;
        const bool odd = (tig & 1);
        #pragma unroll
        for (int snt = 0; snt < 8; snt++) {
            float v00 = __shfl_sync(0xffffffffu, sacc[snt][0], s1l);
            float v01 = __shfl_sync(0xffffffffu, sacc[snt][1], s1l);
            float v20 = __shfl_sync(0xffffffffu, sacc[snt][2], s1l);
            float v21 = __shfl_sync(0xffffffffu, sacc[snt][3], s1l);
            float w00 = __shfl_sync(0xffffffffu, sacc[snt][0], s2l);
            float w01 = __shfl_sync(0xffffffffu, sacc[snt][1], s2l);
            float w20 = __shfl_sync(0xffffffffu, sacc[snt][2], s2l);
            float w21 = __shfl_sync(0xffffffffu, sacc[snt][3], s2l);
            float af[4];
            af[0] = odd ? v01 : v00;
            af[1] = odd ? v21 : v20;
            af[2] = odd ? w01 : w00;
            af[3] = odd ? w21 : w20;
            #pragma unroll
            for (int nt = 0; nt < 8; nt++) {
                float bf[2];
                bf[0] = Vc[(snt * 8 + tig) * VSTR + nt * 8 + gid];
                bf[1] = Vc[(snt * 8 + tig + 4) * VSTR + nt * 8 + gid];
                mma_tf32(oacc[nt], af, bf);
            }
        }
        __syncthreads();
    }

    const float inv0 = 1.f / l0, inv1 = 1.f / l1;
    float* ob = o + (size_t)(b * Lseq) * Dm + h * HDd;
    #pragma unroll
    for (int nt = 0; nt < 8; nt++) {
        int col = nt * 8 + tig * 2;
        float2 o0 = make_float2(tf32r(oacc[nt][0] * inv0), tf32r(oacc[nt][1] * inv0));
        float2 o1 = make_float2(tf32r(oacc[nt][2] * inv1), tf32r(oacc[nt][3] * inv1));
        *(float2*)&ob[(size_t)r0g * Dm + col] = o0;
        *(float2*)&ob[(size_t)(r0g + 8) * Dm + col] = o1;
    }
}

// ---------------------------------------------------------------------------
// Launch sequence (graph-capturable: kernel launches only)
// ---------------------------------------------------------------------------
extern "C" void kernel_launch(void* const* d_in, const int* in_sizes, int n_in,
                              void* d_out, int out_size) {
    const float* spatial   = (const float*)d_in[0];
    const float* density   = (const float*)d_in[1];
    const float* ce        = (const float*)d_in[2];
    const float* spatial_w = (const float*)d_in[3];
    const float* spatial_b = (const float*)d_in[4];
    const float* cond_w    = (const float*)d_in[5];
    const float* cond_b    = (const float*)d_in[6];
    const float* ln1_g     = (const float*)d_in[7];
    const float* ln1_b     = (const float*)d_in[8];
    const float* qkv_w     = (const float*)d_in[9];
    const float* q_scale   = (const float*)d_in[10];
    const float* k_scale   = (const float*)d_in[11];
    const float* proj_w    = (const float*)d_in[12];
    const float* proj_b    = (const float*)d_in[13];
    const float* dscale    = (const float*)d_in[14];
    const float* dbias     = (const float*)d_in[15];
    const float* ln2_g     = (const float*)d_in[16];
    const float* ln2_b     = (const float*)d_in[17];
    const float* mlp_w1    = (const float*)d_in[18];
    const float* mlp_b1    = (const float*)d_in[19];
    const float* mlp_w2    = (const float*)d_in[20];
    const float* mlp_b2    = (const float*)d_in[21];
    const float* out_w     = (const float*)d_in[22];
    const float* out_b     = (const float*)d_in[23];

    float *x, *h, *qkv, *o, *mlp, *cond;
    float *wspat, *wqkv, *wproj, *wm1, *wm2, *wout;
    float2* rope;
    cudaGetSymbolAddress((void**)&x,      g_x);
    cudaGetSymbolAddress((void**)&h,      g_h);
    cudaGetSymbolAddress((void**)&qkv,    g_qkv);
    cudaGetSymbolAddress((void**)&o,      g_o);
    cudaGetSymbolAddress((void**)&mlp,    g_mlp);
    cudaGetSymbolAddress((void**)&cond,   g_cond);
    cudaGetSymbolAddress((void**)&rope,   g_rope);
    cudaGetSymbolAddress((void**)&wspat,  g_wspat);
    cudaGetSymbolAddress((void**)&wqkv,   g_wqkv);
    cudaGetSymbolAddress((void**)&wproj,  g_wproj);
    cudaGetSymbolAddress((void**)&wm1,    g_wm1);
    cudaGetSymbolAddress((void**)&wm2,    g_wm2);
    cudaGetSymbolAddress((void**)&wout,   g_wout);

    cudaFuncSetAttribute(mma_gemm<true,  false, false, true >, cudaFuncAttributeMaxDynamicSharedMemorySize, GEMM_DSMEM);
    cudaFuncSetAttribute(mma_gemm<false, false, false, false>, cudaFuncAttributeMaxDynamicSharedMemorySize, GEMM_DSMEM);
    cudaFuncSetAttribute(mma_gemm<true,  false, true,  false>, cudaFuncAttributeMaxDynamicSharedMemorySize, GEMM_DSMEM);
    cudaFuncSetAttribute(mma_gemm<true,  true,  false, false>, cudaFuncAttributeMaxDynamicSharedMemorySize, GEMM_DSMEM);
    cudaFuncSetAttribute(mma_gemm<true,  false, false, false>, cudaFuncAttributeMaxDynamicSharedMemorySize, GEMM_DSMEM);
    cudaFuncSetAttribute(flash_mma, cudaFuncAttributeMaxDynamicSharedMemorySize, FL_DSMEM);

    // pre-round weights + spatial input (elementwise, position-independent)
    round_kernel<<<(Dm * Dm / 4 + 255) / 256, 256>>>(spatial_w, wspat, Dm * Dm / 4);
    round_kernel<<<(NLn * Dm * 3 * Dm / 4 + 255) / 256, 256>>>(qkv_w, wqkv, NLn * Dm * 3 * Dm / 4);
    round_kernel<<<(NLn * Dm * Dm / 4 + 255) / 256, 256>>>(proj_w, wproj, NLn * Dm * Dm / 4);
    round_kernel<<<(NLn * Dm * MLPd / 4 + 255) / 256, 256>>>(mlp_w1, wm1, NLn * Dm * MLPd / 4);
    round_kernel<<<(NLn * MLPd * Dm / 4 + 255) / 256, 256>>>(mlp_w2, wm2, NLn * MLPd * Dm / 4);
    round_kernel<<<(Dm * Dm / 4 + 255) / 256, 256>>>(out_w, wout, Dm * Dm / 4);
    round_kernel<<<(NTOK * Dm / 4 + 255) / 256, 256>>>(spatial, mlp, NTOK * Dm / 4);

    // RoPE cos/sin table (layer-invariant; bit-identical to in-line fp64)
    rope_table_kernel<<<(Lseq * 32 + 255) / 256, 256>>>(rope);

    cond_kernel<<<(Bsz * Dm + 255) / 256, 256>>>(ce, cond_w, cond_b, cond);
    mma_gemm<true, false, false, true>
        <<<dim3(Dm / TBN, NTOK / TBM), 256, GEMM_DSMEM>>>(
        mlp, wspat, spatial_b, nullptr, cond, x, NTOK, Dm, Dm);

    for (int i = 0; i < NLn; i++) {
        layernorm_kernel<<<NTOK, 256>>>(x, ln1_g + i * Dm, ln1_b + i * Dm, h);

        mma_gemm<false, false, false, false>
            <<<dim3(3 * Dm / TBN, NTOK / TBM), 256, GEMM_DSMEM>>>(
            h, wqkv + (size_t)i * Dm * 3 * Dm, nullptr, nullptr, nullptr,
            qkv, NTOK, 3 * Dm, Dm);

        rmsrope_kernel<<<NTOK, 768>>>(qkv, q_scale + i * HDd, k_scale + i * HDd, rope);

        flash_mma<<<dim3(Lseq / FLQ, NBH), 256, FL_DSMEM>>>(
            qkv, density, dscale, dbias, i, o);

        mma_gemm<true, false, true, false>
            <<<dim3(Dm / TBN, NTOK / TBM), 256, GEMM_DSMEM>>>(
            o, wproj + (size_t)i * Dm * Dm, proj_b + i * Dm, x, nullptr,
            x, NTOK, Dm, Dm);

        layernorm_kernel<<<NTOK, 256>>>(x, ln2_g + i * Dm, ln2_b + i * Dm, h);

        mma_gemm<true, true, false, false>
            <<<dim3(MLPd / TBN, NTOK / TBM), 256, GEMM_DSMEM>>>(
            h, wm1 + (size_t)i * Dm * MLPd, mlp_b1 + i * MLPd, nullptr,
            nullptr, mlp, NTOK, MLPd, Dm);

        mma_gemm<true, false, true, false>
            <<<dim3(Dm / TBN, NTOK / TBM), 256, GEMM_DSMEM>>>(
            mlp, wm2 + (size_t)i * MLPd * Dm, mlp_b2 + i * Dm, x, nullptr,
            x, NTOK, Dm, MLPd);
    }

    // rounded copy of x for the final GEMM (x itself stays exact)
    round_kernel<<<(NTOK * Dm / 4 + 255) / 256, 256>>>(x, h, NTOK * Dm / 4);
    mma_gemm<true, false, false, false>
        <<<dim3(Dm / TBN, NTOK / TBM), 256, GEMM_DSMEM>>>(
        h, wout, out_b, nullptr, nullptr, (float*)d_out, NTOK, Dm, Dm);
}